// round 13
// baseline (speedup 1.0000x reference)
#include <cuda_runtime.h>
#include <cstdint>

// ---------------------------------------------------------------------------
// MPS_33930241638883: 20-qubit staircase, K=1. Bond-dim-2 MPS closed form:
//   psi(x0..x19) = e_{x19}^T . T[x18] ... T[x1] . v(x0)
// T[x]_{t,s} = U[2x+t, 2s], v(x0)_s = U[2x0+s, 0]; x_w = bit (19-w) of n.
// n = G*512 + j: G holds x0..x10, j holds x11..x19 (x19 = j bit 0).
//
// Gate closed form (verified R8): non-I gates are
//   G = ch*(A_p0 x A_p1) - i*sh*(Z x Z),  A_p = Vp^2
// (A_Z=I, A_X=[[0,1],[-1,0]], A_Y=[[0,-i],[-i,0]]); I-gates = rotation kron.
//
// 128 blocks x 512 threads (1 block/SM; 16 warps to hide epilogue latency).
// Per block: 16 groups, 8192 outputs; each thread-half covers 8 groups.
// ---------------------------------------------------------------------------

__device__ __forceinline__ float2 cmul(float2 a, float2 b) {
    return make_float2(a.x * b.x - a.y * b.y, a.x * b.y + a.y * b.x);
}
__device__ __forceinline__ float2 cfma2(float2 a, float2 b, float2 acc) {
    acc.x = fmaf(a.x, b.x, fmaf(-a.y, b.y, acc.x));
    acc.y = fmaf(a.x, b.y, fmaf(a.y, b.x, acc.y));
    return acc;
}
__device__ __forceinline__ int rev4(int v) {
    return ((v & 1) << 3) | ((v & 2) << 1) | ((v & 4) >> 1) | ((v & 8) >> 3);
}

// rotation 2x2: p=1 RX, p=2 RY, p=3 RZ (verified rounds 1-12)
__device__ __forceinline__ float2 rotR(int p, int i, int j, float ch, float sh) {
    if (p == 1) {
        return (i == j) ? make_float2(ch, 0.f) : make_float2(0.f, -sh);
    } else if (p == 2) {
        if (i == j) return make_float2(ch, 0.f);
        return (i == 0) ? make_float2(-sh, 0.f) : make_float2(sh, 0.f);
    } else {
        if (i != j) return make_float2(0.f, 0.f);
        return (j == 0) ? make_float2(ch, -sh) : make_float2(ch, sh);
    }
}

// A_p = Vp^2: p=1 X -> [[0,1],[-1,0]], p=2 Y -> [[0,-i],[-i,0]], p=3 Z -> I
__device__ __forceinline__ float2 sqA(int p, int i, int j) {
    if (p == 1) {
        if (i == j) return make_float2(0.f, 0.f);
        return make_float2((i == 0) ? 1.f : -1.f, 0.f);
    } else if (p == 2) {
        return (i == j) ? make_float2(0.f, 0.f) : make_float2(0.f, -1.f);
    } else {
        return (i == j) ? make_float2(1.f, 0.f) : make_float2(0.f, 0.f);
    }
}

// element (r,c) of gate gi's 4x4 matrix (verified R8)
__device__ __forceinline__ float2 gateElem(int gi, int r, int c, float ch, float sh) {
    int p0, p1;
    if (gi < 3) { p0 = 0; p1 = gi + 1; }
    else        { p0 = ((gi - 3) >> 2) + 1; p1 = (gi - 3) & 3; }
    const int ar = r >> 1, br = r & 1, ac = c >> 1, bc = c & 1;

    if (p0 == 0)
        return (ar == ac) ? rotR(p1, br, bc, ch, sh) : make_float2(0.f, 0.f);
    if (p1 == 0)
        return (br == bc) ? rotR(p0, ar, ac, ch, sh) : make_float2(0.f, 0.f);

    float2 a = cmul(sqA(p0, ar, ac), sqA(p1, br, bc));
    float2 g = make_float2(ch * a.x, ch * a.y);
    if (r == c)
        g.y -= (r == 0 || r == 3) ? sh : -sh;
    return g;
}

__global__ void __launch_bounds__(512, 2) mps_kernel(const float* __restrict__ params,
                                                     float* __restrict__ out) {
    __shared__ float2 bufA[256];   // 16 gate matrices -> U (ends in bufA[0..15])
    __shared__ float2 bufB[256];
    __shared__ float2 sT[8];       // T[b] at b*4 + row*2 + col
    __shared__ float2 sQ[64];      // Q[q] at q*4 + r*2 + c ; q = d3d2d1d0 (d3 left)
    __shared__ float4 sAB[16];     // head (a.re,a.im,b.re,b.im) per group
    __shared__ float2 sL[64];      // left head matrices (16 groups x 4)

    const int tid = threadIdx.x;

    // ---- build 15 gate matrices in parallel (16th = identity) ----
    if (tid < 256) {
        const int m = tid >> 4;          // 0..15
        const int e = tid & 15;
        const int r = e >> 2, c = e & 3;
        float2 g;
        if (m < 15) {
            float th = __ldg(&params[m]);
            float sh, ch;
            sincosf(0.5f * th, &sh, &ch);
            g = gateElem(m, r, c, ch, sh);
        } else {
            g = make_float2((r == c) ? 1.f : 0.f, 0.f);
        }
        bufA[tid] = g;
    }
    __syncthreads();

    // ---- tree-reduce: U = G15 * ... * G0 (4 rounds; T extracted in r4) ----
    {
        float2* src = bufA;
        float2* dst = bufB;
        for (int cnt = 8; cnt >= 1; cnt >>= 1) {
            const int m = tid >> 4;
            if (m < cnt) {
                const int r = (tid >> 2) & 3, c = tid & 3;
                float2 acc = make_float2(0.f, 0.f);
                #pragma unroll
                for (int k = 0; k < 4; k++)
                    acc = cfma2(src[(2 * m + 1) * 16 + r * 4 + k],
                                src[(2 * m) * 16 + k * 4 + c], acc);
                dst[m * 16 + (tid & 15)] = acc;
                if (cnt == 1 && (c & 1) == 0) {
                    // T[b]_{t,s} = U[2b+t, 2s]: b=r>>1, t=r&1, s=c>>1
                    sT[(r >> 1) * 4 + (r & 1) * 2 + (c >> 1)] = acc;
                }
            }
            __syncthreads();
            float2* t = src; src = dst; dst = t;
        }
        // U in bufA[row*4+col], sT populated
    }

    // ---- quad table Q[q] = T[d3].T[d2].T[d1].T[d0], threads 0..63 ----
    if (tid < 64) {
        const int q = tid >> 2;
        const int r = (tid >> 1) & 1, c = tid & 1;
        const int d3 = (q >> 3) & 1, d2 = (q >> 2) & 1;
        const int d1 = (q >> 1) & 1, d0 = q & 1;
        float2 yl0 = cfma2(sT[d3 * 4 + r * 2 + 1], sT[d2 * 4 + 2 + 0],
                           cmul(sT[d3 * 4 + r * 2 + 0], sT[d2 * 4 + 0]));
        float2 yl1 = cfma2(sT[d3 * 4 + r * 2 + 1], sT[d2 * 4 + 2 + 1],
                           cmul(sT[d3 * 4 + r * 2 + 0], sT[d2 * 4 + 1]));
        float2 yr0 = cfma2(sT[d1 * 4 + 0 * 2 + 1], sT[d0 * 4 + 2 + c],
                           cmul(sT[d1 * 4 + 0 * 2 + 0], sT[d0 * 4 + c]));
        float2 yr1 = cfma2(sT[d1 * 4 + 1 * 2 + 1], sT[d0 * 4 + 2 + c],
                           cmul(sT[d1 * 4 + 1 * 2 + 0], sT[d0 * 4 + c]));
        sQ[q * 4 + r * 2 + c] = cfma2(yl1, yr1, cmul(yl0, yr0));
    }
    __syncthreads();

    // ---- heads (warp 0, split-parallel), 16 groups:
    //      ab(G) = [T[x10].Q[x9..x6]] . [Q[x5..x2].(T[x1].v(x0))] ----
    if (tid < 32) {
        const int lane = tid;
        if (lane >= 16) {
            // left L = T[x10] . Q[x9x8x7x6]
            const int gl = lane - 16;
            const int G = blockIdx.x * 16 + gl;
            const int q = rev4((G >> 1) & 15) * 4;
            const int b = (G & 1) * 4;
            const int o = gl * 4;
            sL[o + 0] = cfma2(sT[b + 1], sQ[q + 2], cmul(sT[b + 0], sQ[q + 0]));
            sL[o + 1] = cfma2(sT[b + 1], sQ[q + 3], cmul(sT[b + 0], sQ[q + 1]));
            sL[o + 2] = cfma2(sT[b + 3], sQ[q + 2], cmul(sT[b + 2], sQ[q + 0]));
            sL[o + 3] = cfma2(sT[b + 3], sQ[q + 3], cmul(sT[b + 2], sQ[q + 1]));
        }
        float2 w0, w1;
        if (lane < 16) {
            // right w = Q[x5x4x3x2] . (T[x1] . v(x0))
            const int G = blockIdx.x * 16 + lane;
            const int x0 = (G >> 10) & 1;
            w0 = bufA[(2 * x0 + 0) * 4 + 0];   // v(x0)_s = U[2x0+s, 0]
            w1 = bufA[(2 * x0 + 1) * 4 + 0];
            {
                const int b = ((G >> 9) & 1) * 4;
                float2 n0 = cfma2(sT[b + 1], w1, cmul(sT[b + 0], w0));
                float2 n1 = cfma2(sT[b + 3], w1, cmul(sT[b + 2], w0));
                w0 = n0; w1 = n1;
            }
            {
                const int q = rev4((G >> 5) & 15) * 4;
                float2 n0 = cfma2(sQ[q + 1], w1, cmul(sQ[q + 0], w0));
                float2 n1 = cfma2(sQ[q + 3], w1, cmul(sQ[q + 2], w0));
                w0 = n0; w1 = n1;
            }
        }
        __syncwarp();
        if (lane < 16) {
            const int o = lane * 4;
            float2 ha = cfma2(sL[o + 1], w1, cmul(sL[o + 0], w0));
            float2 hb = cfma2(sL[o + 3], w1, cmul(sL[o + 2], w0));
            sAB[lane] = make_float4(ha.x, ha.y, hb.x, hb.y);
        }
    }

    // ---- per-thread tail matrix O = Q[qL] . Q[qR]  (j = 2*t, 2*t+1) ----
    // t = tid & 255; bit i of t = x_{18-i}: qL = rev4(t&15), qR = rev4(t>>4)
    const int t  = tid & 255;
    const int qL = rev4(t & 15) * 4;
    const int qR = rev4((t >> 4) & 15) * 4;
    const float2 l00 = sQ[qL + 0], l01 = sQ[qL + 1], l10 = sQ[qL + 2], l11 = sQ[qL + 3];
    const float2 r00 = sQ[qR + 0], r01 = sQ[qR + 1], r10 = sQ[qR + 2], r11 = sQ[qR + 3];
    const float2 o00 = cfma2(l01, r10, cmul(l00, r00));
    const float2 o01 = cfma2(l01, r11, cmul(l00, r01));
    const float2 o10 = cfma2(l11, r10, cmul(l10, r00));
    const float2 o11 = cfma2(l11, r11, cmul(l10, r01));

    __syncthreads();

    // ---- epilogue: each half covers 8 groups; coalesced float2 stores ----
    const int gbase = (tid >> 8) * 8;            // half 0 -> groups 0..7, half 1 -> 8..15
    const long base = (long)blockIdx.x * 8192 + (long)gbase * 512 + 2 * t;
    #pragma unroll
    for (int gi = 0; gi < 8; gi++) {
        const float4 h = sAB[gbase + gi];
        const float2 a = make_float2(h.x, h.y);
        const float2 b = make_float2(h.z, h.w);
        float2 pA = cfma2(o01, b, cmul(o00, a));   // row 0 -> x19 = 0
        float2 pB = cfma2(o11, b, cmul(o10, a));   // row 1 -> x19 = 1
        float2 res;
        res.x = fmaf(pA.x, pA.x, pA.y * pA.y);
        res.y = fmaf(pB.x, pB.x, pB.y * pB.y);
        *(float2*)(out + base + gi * 512) = res;
    }
}

extern "C" void kernel_launch(void* const* d_in, const int* in_sizes, int n_in,
                              void* d_out, int out_size) {
    const float* params = (const float*)d_in[0];
    float* out = (float*)d_out;
    mps_kernel<<<128, 512>>>(params, out);
}

// round 14
// speedup vs baseline: 1.1486x; 1.1486x over previous
#include <cuda_runtime.h>
#include <cstdint>

// ---------------------------------------------------------------------------
// MPS_33930241638883: 20-qubit staircase, K=1. Bond-dim-2 MPS closed form:
//   psi(x0..x19) = e_{x19}^T . T[x18] ... T[x1] . v(x0)
// T[x]_{t,s} = U[2x+t, 2s], v(x0)_s = U[2x0+s, 0]; x_w = bit (19-w) of n.
// n = G*512 + j: G holds x0..x10, j holds x11..x19 (x19 = j bit 0).
//
// Gate closed form (verified R8): non-I gates are
//   G = ch*(A_p0 x A_p1) - i*sh*(Z x Z),  A_p = Vp^2
// (A_Z=I, A_X=[[0,1],[-1,0]], A_Y=[[0,-i],[-i,0]]); I-gates = rotation kron.
//
// FINAL (= round-11 kernel, the measured ncu optimum 6.08us):
// 128 blocks x 256 threads (1 block/SM -> zero prologue contention).
// Per block: 16 groups, 8192 outputs.
//  - 16 gate matrices in parallel, 4-round tree matmul -> U (T in round 4)
//  - quad table Q[d3d2d1d0] = T[d3]T[d2]T[d1]T[d0] (64 threads)
//  - split-parallel heads for 16 groups (warp 0)
//  - per-thread tail matrix O = Q.Q reused for 16 groups; 32 outputs,
//    16 coalesced float2 stores
// Grid sweep measured: 1024->8.10, 512->6.50, 256->6.21, 128->6.08 (ncu us).
// ---------------------------------------------------------------------------

__device__ __forceinline__ float2 cmul(float2 a, float2 b) {
    return make_float2(a.x * b.x - a.y * b.y, a.x * b.y + a.y * b.x);
}
__device__ __forceinline__ float2 cfma2(float2 a, float2 b, float2 acc) {
    acc.x = fmaf(a.x, b.x, fmaf(-a.y, b.y, acc.x));
    acc.y = fmaf(a.x, b.y, fmaf(a.y, b.x, acc.y));
    return acc;
}
__device__ __forceinline__ int rev4(int v) {
    return ((v & 1) << 3) | ((v & 2) << 1) | ((v & 4) >> 1) | ((v & 8) >> 3);
}

// rotation 2x2: p=1 RX, p=2 RY, p=3 RZ (verified rounds 1-13)
__device__ __forceinline__ float2 rotR(int p, int i, int j, float ch, float sh) {
    if (p == 1) {
        return (i == j) ? make_float2(ch, 0.f) : make_float2(0.f, -sh);
    } else if (p == 2) {
        if (i == j) return make_float2(ch, 0.f);
        return (i == 0) ? make_float2(-sh, 0.f) : make_float2(sh, 0.f);
    } else {
        if (i != j) return make_float2(0.f, 0.f);
        return (j == 0) ? make_float2(ch, -sh) : make_float2(ch, sh);
    }
}

// A_p = Vp^2: p=1 X -> [[0,1],[-1,0]], p=2 Y -> [[0,-i],[-i,0]], p=3 Z -> I
__device__ __forceinline__ float2 sqA(int p, int i, int j) {
    if (p == 1) {
        if (i == j) return make_float2(0.f, 0.f);
        return make_float2((i == 0) ? 1.f : -1.f, 0.f);
    } else if (p == 2) {
        return (i == j) ? make_float2(0.f, 0.f) : make_float2(0.f, -1.f);
    } else {
        return (i == j) ? make_float2(1.f, 0.f) : make_float2(0.f, 0.f);
    }
}

// element (r,c) of gate gi's 4x4 matrix (verified R8)
__device__ __forceinline__ float2 gateElem(int gi, int r, int c, float ch, float sh) {
    int p0, p1;
    if (gi < 3) { p0 = 0; p1 = gi + 1; }
    else        { p0 = ((gi - 3) >> 2) + 1; p1 = (gi - 3) & 3; }
    const int ar = r >> 1, br = r & 1, ac = c >> 1, bc = c & 1;

    if (p0 == 0)
        return (ar == ac) ? rotR(p1, br, bc, ch, sh) : make_float2(0.f, 0.f);
    if (p1 == 0)
        return (br == bc) ? rotR(p0, ar, ac, ch, sh) : make_float2(0.f, 0.f);

    float2 a = cmul(sqA(p0, ar, ac), sqA(p1, br, bc));
    float2 g = make_float2(ch * a.x, ch * a.y);
    if (r == c)
        g.y -= (r == 0 || r == 3) ? sh : -sh;
    return g;
}

__global__ void __launch_bounds__(256, 8) mps_kernel(const float* __restrict__ params,
                                                     float* __restrict__ out) {
    __shared__ float2 bufA[256];   // 16 gate matrices -> U (ends in bufA[0..15])
    __shared__ float2 bufB[256];
    __shared__ float2 sT[8];       // T[b] at b*4 + row*2 + col
    __shared__ float2 sQ[64];      // Q[q] at q*4 + r*2 + c ; q = d3d2d1d0 (d3 left)
    __shared__ float2 sAB[32];     // head vectors (16 groups x 2)
    __shared__ float2 sL[64];      // left head matrices (16 groups x 4)

    const int tid = threadIdx.x;

    // ---- build 15 gate matrices in parallel (16th = identity) ----
    {
        const int m = tid >> 4;          // 0..15
        const int e = tid & 15;
        const int r = e >> 2, c = e & 3;
        float2 g;
        if (m < 15) {
            float th = __ldg(&params[m]);
            float sh, ch;
            sincosf(0.5f * th, &sh, &ch);
            g = gateElem(m, r, c, ch, sh);
        } else {
            g = make_float2((r == c) ? 1.f : 0.f, 0.f);
        }
        bufA[tid] = g;
    }
    __syncthreads();

    // ---- tree-reduce: U = G15 * ... * G0 (4 rounds; T extracted in r4) ----
    {
        float2* src = bufA;
        float2* dst = bufB;
        for (int cnt = 8; cnt >= 1; cnt >>= 1) {
            const int m = tid >> 4;
            if (m < cnt) {
                const int r = (tid >> 2) & 3, c = tid & 3;
                float2 acc = make_float2(0.f, 0.f);
                #pragma unroll
                for (int k = 0; k < 4; k++)
                    acc = cfma2(src[(2 * m + 1) * 16 + r * 4 + k],
                                src[(2 * m) * 16 + k * 4 + c], acc);
                dst[m * 16 + (tid & 15)] = acc;
                if (cnt == 1 && (c & 1) == 0) {
                    // T[b]_{t,s} = U[2b+t, 2s]: b=r>>1, t=r&1, s=c>>1
                    sT[(r >> 1) * 4 + (r & 1) * 2 + (c >> 1)] = acc;
                }
            }
            __syncthreads();
            float2* t = src; src = dst; dst = t;
        }
        // U in bufA[row*4+col], sT populated
    }

    // ---- quad table Q[q] = T[d3].T[d2].T[d1].T[d0], threads 0..63 ----
    if (tid < 64) {
        const int q = tid >> 2;
        const int r = (tid >> 1) & 1, c = tid & 1;
        const int d3 = (q >> 3) & 1, d2 = (q >> 2) & 1;
        const int d1 = (q >> 1) & 1, d0 = q & 1;
        float2 yl0 = cfma2(sT[d3 * 4 + r * 2 + 1], sT[d2 * 4 + 2 + 0],
                           cmul(sT[d3 * 4 + r * 2 + 0], sT[d2 * 4 + 0]));
        float2 yl1 = cfma2(sT[d3 * 4 + r * 2 + 1], sT[d2 * 4 + 2 + 1],
                           cmul(sT[d3 * 4 + r * 2 + 0], sT[d2 * 4 + 1]));
        float2 yr0 = cfma2(sT[d1 * 4 + 0 * 2 + 1], sT[d0 * 4 + 2 + c],
                           cmul(sT[d1 * 4 + 0 * 2 + 0], sT[d0 * 4 + c]));
        float2 yr1 = cfma2(sT[d1 * 4 + 1 * 2 + 1], sT[d0 * 4 + 2 + c],
                           cmul(sT[d1 * 4 + 1 * 2 + 0], sT[d0 * 4 + c]));
        sQ[q * 4 + r * 2 + c] = cfma2(yl1, yr1, cmul(yl0, yr0));
    }
    __syncthreads();

    // ---- heads (warp 0, split-parallel), 16 groups:
    //      ab(G) = [T[x10].Q[x9..x6]] . [Q[x5..x2].(T[x1].v(x0))] ----
    if (tid < 32) {
        const int lane = tid;
        if (lane >= 16) {
            // left L = T[x10] . Q[x9x8x7x6]
            const int gl = lane - 16;
            const int G = blockIdx.x * 16 + gl;
            const int q = rev4((G >> 1) & 15) * 4;
            const int b = (G & 1) * 4;
            const int o = gl * 4;
            sL[o + 0] = cfma2(sT[b + 1], sQ[q + 2], cmul(sT[b + 0], sQ[q + 0]));
            sL[o + 1] = cfma2(sT[b + 1], sQ[q + 3], cmul(sT[b + 0], sQ[q + 1]));
            sL[o + 2] = cfma2(sT[b + 3], sQ[q + 2], cmul(sT[b + 2], sQ[q + 0]));
            sL[o + 3] = cfma2(sT[b + 3], sQ[q + 3], cmul(sT[b + 2], sQ[q + 1]));
        }
        float2 w0, w1;
        if (lane < 16) {
            // right w = Q[x5x4x3x2] . (T[x1] . v(x0))
            const int G = blockIdx.x * 16 + lane;
            const int x0 = (G >> 10) & 1;
            w0 = bufA[(2 * x0 + 0) * 4 + 0];   // v(x0)_s = U[2x0+s, 0]
            w1 = bufA[(2 * x0 + 1) * 4 + 0];
            {
                const int b = ((G >> 9) & 1) * 4;
                float2 n0 = cfma2(sT[b + 1], w1, cmul(sT[b + 0], w0));
                float2 n1 = cfma2(sT[b + 3], w1, cmul(sT[b + 2], w0));
                w0 = n0; w1 = n1;
            }
            {
                const int q = rev4((G >> 5) & 15) * 4;
                float2 n0 = cfma2(sQ[q + 1], w1, cmul(sQ[q + 0], w0));
                float2 n1 = cfma2(sQ[q + 3], w1, cmul(sQ[q + 2], w0));
                w0 = n0; w1 = n1;
            }
        }
        __syncwarp();
        if (lane < 16) {
            const int o = lane * 4;
            sAB[lane * 2 + 0] = cfma2(sL[o + 1], w1, cmul(sL[o + 0], w0));
            sAB[lane * 2 + 1] = cfma2(sL[o + 3], w1, cmul(sL[o + 2], w0));
        }
    }

    // ---- per-thread tail matrix O = Q[qL] . Q[qR]  (j = 2*tid, 2*tid+1) ----
    // (before the barrier; depends only on sQ)
    // t bit i = x_{18-i}: qL = x18x17x16x15 = rev4(t&15), qR = x14..x11 = rev4(t>>4)
    const int qL = rev4(tid & 15) * 4;
    const int qR = rev4((tid >> 4) & 15) * 4;
    const float2 l00 = sQ[qL + 0], l01 = sQ[qL + 1], l10 = sQ[qL + 2], l11 = sQ[qL + 3];
    const float2 r00 = sQ[qR + 0], r01 = sQ[qR + 1], r10 = sQ[qR + 2], r11 = sQ[qR + 3];
    const float2 o00 = cfma2(l01, r10, cmul(l00, r00));
    const float2 o01 = cfma2(l01, r11, cmul(l00, r01));
    const float2 o10 = cfma2(l11, r10, cmul(l10, r00));
    const float2 o11 = cfma2(l11, r11, cmul(l10, r01));

    __syncthreads();

    // ---- epilogue: 16 groups x 2 outputs, coalesced float2 stores ----
    const long base = (long)blockIdx.x * 8192 + 2 * tid;
    #pragma unroll
    for (int gl = 0; gl < 16; gl++) {
        const float2 a = sAB[gl * 2 + 0];
        const float2 b = sAB[gl * 2 + 1];
        float2 pA = cfma2(o01, b, cmul(o00, a));   // row 0 -> x19 = 0
        float2 pB = cfma2(o11, b, cmul(o10, a));   // row 1 -> x19 = 1
        float2 res;
        res.x = fmaf(pA.x, pA.x, pA.y * pA.y);
        res.y = fmaf(pB.x, pB.x, pB.y * pB.y);
        *(float2*)(out + base + gl * 512) = res;
    }
}

extern "C" void kernel_launch(void* const* d_in, const int* in_sizes, int n_in,
                              void* d_out, int out_size) {
    const float* params = (const float*)d_in[0];
    float* out = (float*)d_out;
    mps_kernel<<<128, 256>>>(params, out);
}

// round 15
// speedup vs baseline: 1.2319x; 1.0725x over previous
#include <cuda_runtime.h>
#include <cstdint>

// ---------------------------------------------------------------------------
// MPS_33930241638883: 20-qubit staircase, K=1. Bond-dim-2 MPS closed form:
//   psi(x0..x19) = e_{x19}^T . T[x18] ... T[x1] . v(x0)
// T[x]_{t,s} = U[2x+t, 2s], v(x0)_s = U[2x0+s, 0]; x_w = bit (19-w) of n.
// n = G*512 + j: G holds x0..x10, j holds x11..x19 (x19 = j bit 0).
//
// Gate closed form (verified R8): non-I gates are
//   G = ch*(A_p0 x A_p1) - i*sh*(Z x Z),  A_p = Vp^2
// (A_Z=I, A_X=[[0,1],[-1,0]], A_Y=[[0,-i],[-i,0]]); I-gates = rotation kron.
//
// R15: Hermitian-form epilogue. |x a + y b|^2 = |x|^2 A + |y|^2 B
//   + 2 Re((x conj y)(a conj b)); per-group float4 (A, B, Re C, Im C),
// per-thread row coefficients precomputed once -> 16 x (LDS.128 + 8 FMA +
// STG.64) epilogue (was 2 LDS.64 + 22 FMA per iter).
//
// 128 blocks x 256 threads (1 block/SM, measured grid optimum).
// ---------------------------------------------------------------------------

__device__ __forceinline__ float2 cmul(float2 a, float2 b) {
    return make_float2(a.x * b.x - a.y * b.y, a.x * b.y + a.y * b.x);
}
__device__ __forceinline__ float2 cfma2(float2 a, float2 b, float2 acc) {
    acc.x = fmaf(a.x, b.x, fmaf(-a.y, b.y, acc.x));
    acc.y = fmaf(a.x, b.y, fmaf(a.y, b.x, acc.y));
    return acc;
}
__device__ __forceinline__ int rev4(int v) {
    return ((v & 1) << 3) | ((v & 2) << 1) | ((v & 4) >> 1) | ((v & 8) >> 3);
}

// rotation 2x2: p=1 RX, p=2 RY, p=3 RZ (verified rounds 1-14)
__device__ __forceinline__ float2 rotR(int p, int i, int j, float ch, float sh) {
    if (p == 1) {
        return (i == j) ? make_float2(ch, 0.f) : make_float2(0.f, -sh);
    } else if (p == 2) {
        if (i == j) return make_float2(ch, 0.f);
        return (i == 0) ? make_float2(-sh, 0.f) : make_float2(sh, 0.f);
    } else {
        if (i != j) return make_float2(0.f, 0.f);
        return (j == 0) ? make_float2(ch, -sh) : make_float2(ch, sh);
    }
}

// A_p = Vp^2: p=1 X -> [[0,1],[-1,0]], p=2 Y -> [[0,-i],[-i,0]], p=3 Z -> I
__device__ __forceinline__ float2 sqA(int p, int i, int j) {
    if (p == 1) {
        if (i == j) return make_float2(0.f, 0.f);
        return make_float2((i == 0) ? 1.f : -1.f, 0.f);
    } else if (p == 2) {
        return (i == j) ? make_float2(0.f, 0.f) : make_float2(0.f, -1.f);
    } else {
        return (i == j) ? make_float2(1.f, 0.f) : make_float2(0.f, 0.f);
    }
}

// element (r,c) of gate gi's 4x4 matrix (verified R8)
__device__ __forceinline__ float2 gateElem(int gi, int r, int c, float ch, float sh) {
    int p0, p1;
    if (gi < 3) { p0 = 0; p1 = gi + 1; }
    else        { p0 = ((gi - 3) >> 2) + 1; p1 = (gi - 3) & 3; }
    const int ar = r >> 1, br = r & 1, ac = c >> 1, bc = c & 1;

    if (p0 == 0)
        return (ar == ac) ? rotR(p1, br, bc, ch, sh) : make_float2(0.f, 0.f);
    if (p1 == 0)
        return (br == bc) ? rotR(p0, ar, ac, ch, sh) : make_float2(0.f, 0.f);

    float2 a = cmul(sqA(p0, ar, ac), sqA(p1, br, bc));
    float2 g = make_float2(ch * a.x, ch * a.y);
    if (r == c)
        g.y -= (r == 0 || r == 3) ? sh : -sh;
    return g;
}

__global__ void __launch_bounds__(256, 8) mps_kernel(const float* __restrict__ params,
                                                     float* __restrict__ out) {
    __shared__ float2 bufA[256];   // 16 gate matrices -> U (ends in bufA[0..15])
    __shared__ float2 bufB[256];
    __shared__ float2 sT[8];       // T[b] at b*4 + row*2 + col
    __shared__ float2 sQ[64];      // Q[q] at q*4 + r*2 + c ; q = d3d2d1d0 (d3 left)
    __shared__ float4 sH[16];      // per-group Hermitian data (|a|^2,|b|^2,ReC,ImC)
    __shared__ float2 sL[64];      // left head matrices (16 groups x 4)

    const int tid = threadIdx.x;

    // ---- build 15 gate matrices in parallel (16th = identity) ----
    {
        const int m = tid >> 4;          // 0..15
        const int e = tid & 15;
        const int r = e >> 2, c = e & 3;
        float2 g;
        if (m < 15) {
            float th = __ldg(&params[m]);
            float sh, ch;
            sincosf(0.5f * th, &sh, &ch);
            g = gateElem(m, r, c, ch, sh);
        } else {
            g = make_float2((r == c) ? 1.f : 0.f, 0.f);
        }
        bufA[tid] = g;
    }
    __syncthreads();

    // ---- tree-reduce: U = G15 * ... * G0 (4 rounds; T extracted in r4) ----
    {
        float2* src = bufA;
        float2* dst = bufB;
        for (int cnt = 8; cnt >= 1; cnt >>= 1) {
            const int m = tid >> 4;
            if (m < cnt) {
                const int r = (tid >> 2) & 3, c = tid & 3;
                float2 acc = make_float2(0.f, 0.f);
                #pragma unroll
                for (int k = 0; k < 4; k++)
                    acc = cfma2(src[(2 * m + 1) * 16 + r * 4 + k],
                                src[(2 * m) * 16 + k * 4 + c], acc);
                dst[m * 16 + (tid & 15)] = acc;
                if (cnt == 1 && (c & 1) == 0) {
                    // T[b]_{t,s} = U[2b+t, 2s]: b=r>>1, t=r&1, s=c>>1
                    sT[(r >> 1) * 4 + (r & 1) * 2 + (c >> 1)] = acc;
                }
            }
            __syncthreads();
            float2* t = src; src = dst; dst = t;
        }
        // U in bufA[row*4+col], sT populated
    }

    // ---- quad table Q[q] = T[d3].T[d2].T[d1].T[d0], threads 0..63 ----
    if (tid < 64) {
        const int q = tid >> 2;
        const int r = (tid >> 1) & 1, c = tid & 1;
        const int d3 = (q >> 3) & 1, d2 = (q >> 2) & 1;
        const int d1 = (q >> 1) & 1, d0 = q & 1;
        float2 yl0 = cfma2(sT[d3 * 4 + r * 2 + 1], sT[d2 * 4 + 2 + 0],
                           cmul(sT[d3 * 4 + r * 2 + 0], sT[d2 * 4 + 0]));
        float2 yl1 = cfma2(sT[d3 * 4 + r * 2 + 1], sT[d2 * 4 + 2 + 1],
                           cmul(sT[d3 * 4 + r * 2 + 0], sT[d2 * 4 + 1]));
        float2 yr0 = cfma2(sT[d1 * 4 + 0 * 2 + 1], sT[d0 * 4 + 2 + c],
                           cmul(sT[d1 * 4 + 0 * 2 + 0], sT[d0 * 4 + c]));
        float2 yr1 = cfma2(sT[d1 * 4 + 1 * 2 + 1], sT[d0 * 4 + 2 + c],
                           cmul(sT[d1 * 4 + 1 * 2 + 0], sT[d0 * 4 + c]));
        sQ[q * 4 + r * 2 + c] = cfma2(yl1, yr1, cmul(yl0, yr0));
    }
    __syncthreads();

    // ---- heads (warp 0, split-parallel), 16 groups:
    //      ab(G) = [T[x10].Q[x9..x6]] . [Q[x5..x2].(T[x1].v(x0))] ----
    if (tid < 32) {
        const int lane = tid;
        if (lane >= 16) {
            // left L = T[x10] . Q[x9x8x7x6]
            const int gl = lane - 16;
            const int G = blockIdx.x * 16 + gl;
            const int q = rev4((G >> 1) & 15) * 4;
            const int b = (G & 1) * 4;
            const int o = gl * 4;
            sL[o + 0] = cfma2(sT[b + 1], sQ[q + 2], cmul(sT[b + 0], sQ[q + 0]));
            sL[o + 1] = cfma2(sT[b + 1], sQ[q + 3], cmul(sT[b + 0], sQ[q + 1]));
            sL[o + 2] = cfma2(sT[b + 3], sQ[q + 2], cmul(sT[b + 2], sQ[q + 0]));
            sL[o + 3] = cfma2(sT[b + 3], sQ[q + 3], cmul(sT[b + 2], sQ[q + 1]));
        }
        float2 w0, w1;
        if (lane < 16) {
            // right w = Q[x5x4x3x2] . (T[x1] . v(x0))
            const int G = blockIdx.x * 16 + lane;
            const int x0 = (G >> 10) & 1;
            w0 = bufA[(2 * x0 + 0) * 4 + 0];   // v(x0)_s = U[2x0+s, 0]
            w1 = bufA[(2 * x0 + 1) * 4 + 0];
            {
                const int b = ((G >> 9) & 1) * 4;
                float2 n0 = cfma2(sT[b + 1], w1, cmul(sT[b + 0], w0));
                float2 n1 = cfma2(sT[b + 3], w1, cmul(sT[b + 2], w0));
                w0 = n0; w1 = n1;
            }
            {
                const int q = rev4((G >> 5) & 15) * 4;
                float2 n0 = cfma2(sQ[q + 1], w1, cmul(sQ[q + 0], w0));
                float2 n1 = cfma2(sQ[q + 3], w1, cmul(sQ[q + 2], w0));
                w0 = n0; w1 = n1;
            }
        }
        __syncwarp();
        if (lane < 16) {
            const int o = lane * 4;
            float2 ha = cfma2(sL[o + 1], w1, cmul(sL[o + 0], w0));
            float2 hb = cfma2(sL[o + 3], w1, cmul(sL[o + 2], w0));
            // Hermitian data: A=|a|^2, B=|b|^2, C = a * conj(b)
            float A = fmaf(ha.x, ha.x, ha.y * ha.y);
            float B = fmaf(hb.x, hb.x, hb.y * hb.y);
            float Cr = fmaf(ha.x, hb.x, ha.y * hb.y);
            float Ci = fmaf(ha.y, hb.x, -ha.x * hb.y);
            sH[lane] = make_float4(A, B, Cr, Ci);
        }
    }

    // ---- per-thread tail matrix O = Q[qL] . Q[qR]  (j = 2*tid, 2*tid+1) ----
    // t bit i = x_{18-i}: qL = x18x17x16x15 = rev4(t&15), qR = x14..x11 = rev4(t>>4)
    const int qL = rev4(tid & 15) * 4;
    const int qR = rev4((tid >> 4) & 15) * 4;
    const float2 l00 = sQ[qL + 0], l01 = sQ[qL + 1], l10 = sQ[qL + 2], l11 = sQ[qL + 3];
    const float2 r00 = sQ[qR + 0], r01 = sQ[qR + 1], r10 = sQ[qR + 2], r11 = sQ[qR + 3];
    const float2 o00 = cfma2(l01, r10, cmul(l00, r00));
    const float2 o01 = cfma2(l01, r11, cmul(l00, r01));
    const float2 o10 = cfma2(l11, r10, cmul(l10, r00));
    const float2 o11 = cfma2(l11, r11, cmul(l10, r01));

    // Hermitian row coefficients (once per thread):
    // row A (x19=0): |psi|^2 = fA0*A + fA1*B + uA2r*Cr - uA2i*Ci
    //   with u = o00 * conj(o01), uA2r = 2*u.re, uA2i = 2*u.im
    const float fA0  = fmaf(o00.x, o00.x, o00.y * o00.y);
    const float fA1  = fmaf(o01.x, o01.x, o01.y * o01.y);
    const float uA2r = 2.f * fmaf(o00.x, o01.x, o00.y * o01.y);
    const float uA2i = 2.f * fmaf(o00.y, o01.x, -o00.x * o01.y);
    const float fB0  = fmaf(o10.x, o10.x, o10.y * o10.y);
    const float fB1  = fmaf(o11.x, o11.x, o11.y * o11.y);
    const float uB2r = 2.f * fmaf(o10.x, o11.x, o10.y * o11.y);
    const float uB2i = 2.f * fmaf(o10.y, o11.x, -o10.x * o11.y);

    __syncthreads();

    // ---- epilogue: 16 groups x 2 outputs; LDS.128 + 8 FMA + STG.64 each ----
    const long base = (long)blockIdx.x * 8192 + 2 * tid;
    #pragma unroll
    for (int gl = 0; gl < 16; gl++) {
        const float4 h = sH[gl];
        float2 res;
        res.x = fmaf(fA0, h.x, fmaf(fA1, h.y, fmaf(uA2r, h.z, -uA2i * h.w)));
        res.y = fmaf(fB0, h.x, fmaf(fB1, h.y, fmaf(uB2r, h.z, -uB2i * h.w)));
        *(float2*)(out + base + gl * 512) = res;
    }
}

extern "C" void kernel_launch(void* const* d_in, const int* in_sizes, int n_in,
                              void* d_out, int out_size) {
    const float* params = (const float*)d_in[0];
    float* out = (float*)d_out;
    mps_kernel<<<128, 256>>>(params, out);
}